// round 12
// baseline (speedup 1.0000x reference)
#include <cuda_runtime.h>
#include <cstdint>

#define N_DIM 1024
#define M_DIM 2048
#define P_DIM 512
#define Q_DIM 128
#define KAPPA 0.99f
#define TOL   3e-6f
#define BFSW  1e-3f
#define MAXIT 300
#define NBLK  128

#define KC   32
#define LDA  40                  // tf32 path row stride (floats)
#define SM_BUF 5120              // 128 * LDA floats per buffer
#define DSMEM_BYTES (40960 * 4)  // tf32 full layout: Ah[2],Al[2],Xh[2],Xl[2]

#define LDAB 24                  // bf16 path row stride (uint32 units)
#define SMB  3072                // 128 * LDAB uint32 per buffer

// ---------------- device state ----------------
__device__ float g_Ahi[(size_t)N_DIM * N_DIM];
__device__ float g_Alo[(size_t)N_DIM * N_DIM];
__device__ uint32_t g_Abf[(size_t)N_DIM * (N_DIM / 2)];
__device__ float g_BU[(size_t)M_DIM * N_DIM];     // m-major
__device__ float g_X0buf[(size_t)M_DIM * N_DIM];  // ping-pong scratch
__device__ float g_X1buf[(size_t)M_DIM * N_DIM];
__device__ float g_part[8][(size_t)M_DIM * Q_DIM];
__device__ unsigned g_md[MAXIT + 2];
__device__ unsigned g_barcnt;
__device__ unsigned g_x0nz;

// ---------------- helpers ----------------
__device__ __forceinline__ uint32_t f2tf(float x) {
    uint32_t r;
    asm("cvt.rna.tf32.f32 %0, %1;" : "=r"(r) : "f"(x));
    return r;
}
__device__ __forceinline__ float tf(float x) { return __uint_as_float(f2tf(x)); }

__device__ __forceinline__ uint32_t pbf(float lo, float hi) {
    uint32_t r;
    asm("cvt.rn.bf16x2.f32 %0, %1, %2;" : "=r"(r) : "f"(hi), "f"(lo));
    return r;
}

__device__ __forceinline__ void mma8(float* d, const uint32_t* a, const uint32_t* b) {
    asm volatile(
        "mma.sync.aligned.m16n8k8.row.col.f32.tf32.tf32.f32 "
        "{%0,%1,%2,%3},{%4,%5,%6,%7},{%8,%9},{%0,%1,%2,%3};"
        : "+f"(d[0]), "+f"(d[1]), "+f"(d[2]), "+f"(d[3])
        : "r"(a[0]), "r"(a[1]), "r"(a[2]), "r"(a[3]), "r"(b[0]), "r"(b[1]));
}
__device__ __forceinline__ void mma16bf(float* d, const uint32_t* a, const uint32_t* b) {
    asm volatile(
        "mma.sync.aligned.m16n8k16.row.col.f32.bf16.bf16.f32 "
        "{%0,%1,%2,%3},{%4,%5,%6,%7},{%8,%9},{%0,%1,%2,%3};"
        : "+f"(d[0]), "+f"(d[1]), "+f"(d[2]), "+f"(d[3])
        : "r"(a[0]), "r"(a[1]), "r"(a[2]), "r"(a[3]), "r"(b[0]), "r"(b[1]));
}

// interleaved store (tf32 floats): within 8-col block, col j -> 2*(j&3)+(j>>2)
__device__ __forceinline__ void perm_st(float* dst, int off, float4 v0, float4 v1) {
    *(float4*)&dst[off]     = make_float4(v0.x, v1.x, v0.y, v1.y);
    *(float4*)&dst[off + 4] = make_float4(v0.z, v1.z, v0.w, v1.w);
}
__device__ __forceinline__ void perm_split(float* hi, float* lo, int off,
                                           float4 v0, float4 v1, int full) {
    float4 h0 = make_float4(tf(v0.x), tf(v0.y), tf(v0.z), tf(v0.w));
    float4 h1 = make_float4(tf(v1.x), tf(v1.y), tf(v1.z), tf(v1.w));
    perm_st(hi, off, h0, h1);
    if (full) {
        float4 l0 = make_float4(tf(v0.x - h0.x), tf(v0.y - h0.y),
                                tf(v0.z - h0.z), tf(v0.w - h0.w));
        float4 l1 = make_float4(tf(v1.x - h1.x), tf(v1.y - h1.y),
                                tf(v1.z - h1.z), tf(v1.w - h1.w));
        perm_st(lo, off, l0, l1);
    }
}
// interleaved store (bf16 u32 pairs): pair index j -> 2*(j&3)+(j>>2)
__device__ __forceinline__ void st_bf(uint32_t* dst, int off, const uint32_t* j) {
    *(uint4*)&dst[off]     = make_uint4(j[0], j[4], j[1], j[5]);
    *(uint4*)&dst[off + 4] = make_uint4(j[2], j[6], j[3], j[7]);
}

// ---------------- 128x128 tf32 GEMM tile (acc += A(128,k) * B(128,k)^T), KC=32 ----------------
template <int PRESPLIT>
__device__ __forceinline__ void gemm_tile(
    const float* __restrict__ Ahi, const float* __restrict__ Alo, int lda,
    const float* __restrict__ Bb, int ldb, int kdim, int full,
    float* __restrict__ sm, float acc[4][4][4])
{
    float* Ah = sm;
    float* Al = sm + 10240;
    float* Xh = sm + 20480;
    float* Xl = sm + 30720;
    int tid = threadIdx.x;
    int warp = tid >> 5, lane = tid & 31;
    int wm = warp >> 2, wn = warp & 3;
    int g = lane >> 2, c = lane & 3;
    int lrow = tid & 127, lh = tid >> 7;
    int sbase = lrow * LDA + lh * 16;

    const float* aph = Ahi + (size_t)lrow * lda + lh * 16;
    const float* apl = Alo + (size_t)lrow * lda + lh * 16;
    const float* xp  = Bb  + (size_t)lrow * ldb + lh * 16;

    float4 a[4], al[4], x[4];
#pragma unroll
    for (int i = 0; i < 4; i++) a[i] = *(const float4*)(aph + 4 * i);
    if (PRESPLIT && full)
#pragma unroll
        for (int i = 0; i < 4; i++) al[i] = *(const float4*)(apl + 4 * i);
#pragma unroll
    for (int i = 0; i < 4; i++) x[i] = *(const float4*)(xp + 4 * i);

    if (PRESPLIT) {
        perm_st(Ah, sbase, a[0], a[1]);
        perm_st(Ah, sbase + 8, a[2], a[3]);
        if (full) {
            perm_st(Al, sbase, al[0], al[1]);
            perm_st(Al, sbase + 8, al[2], al[3]);
        }
    } else {
        perm_split(Ah, Al, sbase, a[0], a[1], full);
        perm_split(Ah, Al, sbase + 8, a[2], a[3], full);
    }
    perm_split(Xh, Xl, sbase, x[0], x[1], full);
    perm_split(Xh, Xl, sbase + 8, x[2], x[3], full);
    __syncthreads();

    int NST = kdim / KC;
    for (int s = 0; s < NST; s++) {
        int ab = (s & 1) * SM_BUF;
        if (s + 1 < NST) {
            int kk = KC * (s + 1);
#pragma unroll
            for (int i = 0; i < 4; i++) a[i] = *(const float4*)(aph + kk + 4 * i);
            if (PRESPLIT && full)
#pragma unroll
                for (int i = 0; i < 4; i++) al[i] = *(const float4*)(apl + kk + 4 * i);
#pragma unroll
            for (int i = 0; i < 4; i++) x[i] = *(const float4*)(xp + kk + 4 * i);
        }
#pragma unroll
        for (int k8 = 0; k8 < KC; k8 += 8) {
            uint32_t ahf[4][4], bhf[4][2];
#pragma unroll
            for (int mi = 0; mi < 4; mi++) {
                int r0 = wm * 64 + mi * 16 + g;
                float2 t0 = *(const float2*)&Ah[ab + r0 * LDA + k8 + 2 * c];
                float2 t1 = *(const float2*)&Ah[ab + (r0 + 8) * LDA + k8 + 2 * c];
                ahf[mi][0] = __float_as_uint(t0.x);
                ahf[mi][1] = __float_as_uint(t1.x);
                ahf[mi][2] = __float_as_uint(t0.y);
                ahf[mi][3] = __float_as_uint(t1.y);
            }
#pragma unroll
            for (int ni = 0; ni < 4; ni++) {
                int n0 = wn * 32 + ni * 8 + g;
                float2 t = *(const float2*)&Xh[ab + n0 * LDA + k8 + 2 * c];
                bhf[ni][0] = __float_as_uint(t.x);
                bhf[ni][1] = __float_as_uint(t.y);
            }
            if (full) {
                uint32_t alf[4][4], blf[4][2];
#pragma unroll
                for (int mi = 0; mi < 4; mi++) {
                    int r0 = wm * 64 + mi * 16 + g;
                    float2 t0 = *(const float2*)&Al[ab + r0 * LDA + k8 + 2 * c];
                    float2 t1 = *(const float2*)&Al[ab + (r0 + 8) * LDA + k8 + 2 * c];
                    alf[mi][0] = __float_as_uint(t0.x);
                    alf[mi][1] = __float_as_uint(t1.x);
                    alf[mi][2] = __float_as_uint(t0.y);
                    alf[mi][3] = __float_as_uint(t1.y);
                }
#pragma unroll
                for (int ni = 0; ni < 4; ni++) {
                    int n0 = wn * 32 + ni * 8 + g;
                    float2 t = *(const float2*)&Xl[ab + n0 * LDA + k8 + 2 * c];
                    blf[ni][0] = __float_as_uint(t.x);
                    blf[ni][1] = __float_as_uint(t.y);
                }
#pragma unroll
                for (int mi = 0; mi < 4; mi++)
#pragma unroll
                    for (int ni = 0; ni < 4; ni++) {
                        mma8(acc[mi][ni], ahf[mi], bhf[ni]);
                        mma8(acc[mi][ni], ahf[mi], blf[ni]);
                        mma8(acc[mi][ni], alf[mi], bhf[ni]);
                    }
            } else {
#pragma unroll
                for (int mi = 0; mi < 4; mi++)
#pragma unroll
                    for (int ni = 0; ni < 4; ni++)
                        mma8(acc[mi][ni], ahf[mi], bhf[ni]);
            }
        }
        if (s + 1 < NST) {
            int nb = ((s + 1) & 1) * SM_BUF + sbase;
            if (PRESPLIT) {
                perm_st(Ah, nb, a[0], a[1]);
                perm_st(Ah, nb + 8, a[2], a[3]);
                if (full) {
                    perm_st(Al, nb, al[0], al[1]);
                    perm_st(Al, nb + 8, al[2], al[3]);
                }
            } else {
                perm_split(Ah, Al, nb, a[0], a[1], full);
                perm_split(Ah, Al, nb + 8, a[2], a[3], full);
            }
            perm_split(Xh, Xl, nb, x[0], x[1], full);
            perm_split(Xh, Xl, nb + 8, x[2], x[3], full);
        }
        __syncthreads();
    }
}

// ---------------- 128x128 bf16 GEMM tile: acc += Abf(128,k) * X(128,k)^T ----------------
__device__ __forceinline__ void gemm_bf16_tile(
    const uint32_t* __restrict__ Abf,          // packed pairs, N_DIM/2 u32 per row
    const float* __restrict__ Xin, int ldx,
    uint32_t* __restrict__ smu, float acc[4][4][4])
{
    uint32_t* As = smu;            // [2][SMB]
    uint32_t* Xs = smu + 2 * SMB;  // [2][SMB]
    int tid = threadIdx.x;
    int warp = tid >> 5, lane = tid & 31;
    int wm = warp >> 2, wn = warp & 3;
    int g = lane >> 2, c = lane & 3;
    int lrow = tid & 127, lh = tid >> 7;
    int sb = lrow * LDAB + lh * 8;

    const uint32_t* ap = Abf + (size_t)lrow * (N_DIM / 2) + lh * 8;
    const float* xp = Xin + (size_t)lrow * ldx + lh * 16;

    uint32_t ja[8], jx[8];
    {
        uint4 t0 = *(const uint4*)ap;
        uint4 t1 = *(const uint4*)(ap + 4);
        ja[0] = t0.x; ja[1] = t0.y; ja[2] = t0.z; ja[3] = t0.w;
        ja[4] = t1.x; ja[5] = t1.y; ja[6] = t1.z; ja[7] = t1.w;
        float4 f0 = *(const float4*)xp,        f1 = *(const float4*)(xp + 4);
        float4 f2 = *(const float4*)(xp + 8),  f3 = *(const float4*)(xp + 12);
        jx[0] = pbf(f0.x, f0.y); jx[1] = pbf(f0.z, f0.w);
        jx[2] = pbf(f1.x, f1.y); jx[3] = pbf(f1.z, f1.w);
        jx[4] = pbf(f2.x, f2.y); jx[5] = pbf(f2.z, f2.w);
        jx[6] = pbf(f3.x, f3.y); jx[7] = pbf(f3.z, f3.w);
    }
    st_bf(As, sb, ja);
    st_bf(Xs, sb, jx);
    __syncthreads();

    const int NSTB = N_DIM / KC;   // 32
    for (int s = 0; s < NSTB; s++) {
        int ab = (s & 1) * SMB;
        if (s + 1 < NSTB) {
            const uint32_t* apn = ap + (s + 1) * 16;
            const float* xpn = xp + (s + 1) * 32;
            uint4 t0 = *(const uint4*)apn;
            uint4 t1 = *(const uint4*)(apn + 4);
            ja[0] = t0.x; ja[1] = t0.y; ja[2] = t0.z; ja[3] = t0.w;
            ja[4] = t1.x; ja[5] = t1.y; ja[6] = t1.z; ja[7] = t1.w;
            float4 f0 = *(const float4*)xpn,        f1 = *(const float4*)(xpn + 4);
            float4 f2 = *(const float4*)(xpn + 8),  f3 = *(const float4*)(xpn + 12);
            jx[0] = pbf(f0.x, f0.y); jx[1] = pbf(f0.z, f0.w);
            jx[2] = pbf(f1.x, f1.y); jx[3] = pbf(f1.z, f1.w);
            jx[4] = pbf(f2.x, f2.y); jx[5] = pbf(f2.z, f2.w);
            jx[6] = pbf(f3.x, f3.y); jx[7] = pbf(f3.z, f3.w);
        }
#pragma unroll
        for (int k16 = 0; k16 < 2; k16++) {
            int kb = k16 * 8;
            uint32_t af[4][4], bff[4][2];
#pragma unroll
            for (int mi = 0; mi < 4; mi++) {
                int r0 = wm * 64 + mi * 16 + g;
                uint2 t0 = *(const uint2*)&As[ab + r0 * LDAB + kb + 2 * c];
                uint2 t1 = *(const uint2*)&As[ab + (r0 + 8) * LDAB + kb + 2 * c];
                af[mi][0] = t0.x; af[mi][1] = t1.x;
                af[mi][2] = t0.y; af[mi][3] = t1.y;
            }
#pragma unroll
            for (int ni = 0; ni < 4; ni++) {
                int n0 = wn * 32 + ni * 8 + g;
                uint2 t = *(const uint2*)&Xs[ab + n0 * LDAB + kb + 2 * c];
                bff[ni][0] = t.x; bff[ni][1] = t.y;
            }
#pragma unroll
            for (int mi = 0; mi < 4; mi++)
#pragma unroll
                for (int ni = 0; ni < 4; ni++)
                    mma16bf(acc[mi][ni], af[mi], bff[ni]);
        }
        if (s + 1 < NSTB) {
            int nb = ((s + 1) & 1) * SMB + sb;
            st_bf(As, nb, ja);
            st_bf(Xs, nb, jx);
        }
        __syncthreads();
    }
}

// ---------------- init ----------------
__global__ void init_kernel() {
    int t = threadIdx.x;
    for (int i = t; i < MAXIT + 2; i += 256) g_md[i] = 0u;
    if (t == 0) { g_barcnt = 0u; g_x0nz = 0u; }
}

// ---------------- grid barrier (target computed ONCE per epoch) ----------------
__device__ __forceinline__ void grid_bar(unsigned& ep, int tid) {
    __syncthreads();
    ep++;
    if (tid == 0) {
        __threadfence();
        atomicAdd(&g_barcnt, 1u);
        unsigned target = ep * NBLK;
        while (atomicAdd(&g_barcnt, 0u) < target) {}
        __threadfence();
    }
    __syncthreads();
}

// ---------------- the whole model in one persistent kernel ----------------
__global__ __launch_bounds__(256, 1) void picard_kernel(
    const float* __restrict__ A, const float* __restrict__ X0,
    const float* __restrict__ B, const float* __restrict__ U,
    const float* __restrict__ Cm, const float* __restrict__ Dm,
    float* __restrict__ outp)
{
    extern __shared__ float sm[];
    uint32_t* smu = (uint32_t*)sm;
    __shared__ float red[8];

    int tid = threadIdx.x;
    int warp = tid >> 5, lane = tid & 31;
    int wm = warp >> 2, wn = warp & 3;
    int g = lane >> 2, c = lane & 3;
    int bid = blockIdx.x;
    int j0 = (bid & 15) * 128;   // m tile
    int i0 = (bid >> 4) * 128;   // n tile
    unsigned ep = 0;

    // ---- phase 0a: projection + tf32/bf16 presplit (rows bid*8 + warp) ----
    {
        int row = bid * 8 + warp;
        const float* ar = A + (size_t)row * N_DIM;
        float s = 0.f;
        for (int c2 = lane; c2 < N_DIM / 2; c2 += 32)
            s += fabsf(ar[2 * c2]) + fabsf(ar[2 * c2 + 1]);
#pragma unroll
        for (int o = 16; o; o >>= 1) s += __shfl_xor_sync(0xffffffffu, s, o);
        float sc = fminf(1.f, KAPPA / fmaxf(s, 1e-12f));
        float* oh = g_Ahi + (size_t)row * N_DIM;
        float* ol = g_Alo + (size_t)row * N_DIM;
        uint32_t* ob = g_Abf + (size_t)row * (N_DIM / 2);
        for (int c2 = lane; c2 < N_DIM / 2; c2 += 32) {
            float v0 = ar[2 * c2] * sc, v1 = ar[2 * c2 + 1] * sc;
            float h0 = tf(v0), h1 = tf(v1);
            oh[2 * c2] = h0; oh[2 * c2 + 1] = h1;
            ol[2 * c2] = tf(v0 - h0); ol[2 * c2 + 1] = tf(v1 - h1);
            ob[c2] = pbf(v0, v1);
        }
    }
    // ---- phase 0b: X0 nonzero scan ----
    {
        size_t base = (size_t)bid * 4096;
        const float4* src = (const float4*)X0;
        unsigned nz = 0u;
        for (int i = tid; i < 4096; i += 256) {
            float4 v = src[base + i];
            nz |= __float_as_uint(v.x) | __float_as_uint(v.y)
                | __float_as_uint(v.z) | __float_as_uint(v.w);
        }
        nz &= 0x7FFFFFFFu;
#pragma unroll
        for (int o = 16; o; o >>= 1) nz |= __shfl_xor_sync(0xffffffffu, nz, o);
        if (lane == 0 && nz) atomicOr(&g_x0nz, 1u);
    }

    float acc[4][4][4];
    // ---- phase 1: BU tile (full 3xTF32); doubles as iteration 0 for X0 == 0 ----
#pragma unroll
    for (int mi = 0; mi < 4; mi++)
#pragma unroll
        for (int ni = 0; ni < 4; ni++)
#pragma unroll
            for (int r = 0; r < 4; r++) acc[mi][ni][r] = 0.f;
    gemm_tile<0>(B + (size_t)i0 * P_DIM, B + (size_t)i0 * P_DIM, P_DIM,
                 U + (size_t)j0 * P_DIM, P_DIM, P_DIM, 1, sm, acc);
    {
        float maxd = 0.f;
#pragma unroll
        for (int mi = 0; mi < 4; mi++)
#pragma unroll
            for (int ni = 0; ni < 4; ni++)
#pragma unroll
                for (int r = 0; r < 4; r++) {
                    int il = wm * 64 + mi * 16 + g + ((r >= 2) ? 8 : 0);
                    int jl = wn * 32 + ni * 8 + 2 * c + (r & 1);
                    size_t adr = (size_t)(j0 + jl) * N_DIM + (i0 + il);
                    float bu = acc[mi][ni][r];
                    g_BU[adr] = bu;
                    float v = fmaxf(bu, 0.f);
                    g_X1buf[adr] = v;        // speculative it0 output (X0 == 0 case)
                    maxd = fmaxf(maxd, v);
                }
#pragma unroll
        for (int o = 16; o; o >>= 1) maxd = fmaxf(maxd, __shfl_xor_sync(0xffffffffu, maxd, o));
        if (lane == 0) red[warp] = maxd;
        __syncthreads();
        if (tid == 0) {
            float m = red[0];
#pragma unroll
            for (int i2 = 1; i2 < 8; i2++) m = fmaxf(m, red[i2]);
            atomicMax(&g_md[0], __float_as_uint(m));
        }
    }
    grid_bar(ep, tid);

    // ---- Picard loop ----
    float* Xb[2] = {g_X0buf, g_X1buf};
    unsigned x0nz = g_x0nz;
    const float* fin = g_X1buf;
    const float* in;
    int outIdx, mdidx = 1, done = 0;
    float md_prev;
    if (!x0nz) {
        float md0 = __uint_as_float(g_md[0]);
        if (md0 <= TOL) done = 1;
        in = g_X1buf; outIdx = 0; md_prev = md0;
    } else {
        in = X0; outIdx = 1; md_prev = 1e30f;
    }

    while (!done && mdidx < MAXIT) {
        float* out = Xb[outIdx];
#pragma unroll
        for (int mi = 0; mi < 4; mi++)
#pragma unroll
            for (int ni = 0; ni < 4; ni++)
#pragma unroll
                for (int r = 0; r < 4; r++) acc[mi][ni][r] = 0.f;

        if (md_prev > BFSW)
            gemm_bf16_tile(g_Abf + (size_t)i0 * (N_DIM / 2),
                           in + (size_t)j0 * N_DIM, N_DIM, smu, acc);
        else
            gemm_tile<1>(g_Ahi + (size_t)i0 * N_DIM, g_Alo + (size_t)i0 * N_DIM, N_DIM,
                         in + (size_t)j0 * N_DIM, N_DIM, N_DIM, 0, sm, acc);

        float maxd = 0.f;
#pragma unroll
        for (int mi = 0; mi < 4; mi++)
#pragma unroll
            for (int ni = 0; ni < 4; ni++)
#pragma unroll
                for (int r = 0; r < 4; r++) {
                    int il = wm * 64 + mi * 16 + g + ((r >= 2) ? 8 : 0);
                    int jl = wn * 32 + ni * 8 + 2 * c + (r & 1);
                    size_t adr = (size_t)(j0 + jl) * N_DIM + (i0 + il);
                    float v = fmaxf(acc[mi][ni][r] + g_BU[adr], 0.f);
                    maxd = fmaxf(maxd, fabsf(v - in[adr]));
                    out[adr] = v;
                }
#pragma unroll
        for (int o = 16; o; o >>= 1) maxd = fmaxf(maxd, __shfl_xor_sync(0xffffffffu, maxd, o));
        if (lane == 0) red[warp] = maxd;
        __syncthreads();
        if (tid == 0) {
            float m = red[0];
#pragma unroll
            for (int i2 = 1; i2 < 8; i2++) m = fmaxf(m, red[i2]);
            atomicMax(&g_md[mdidx], __float_as_uint(m));
        }
        grid_bar(ep, tid);

        float md = __uint_as_float(g_md[mdidx]);
        fin = out;
        if (md <= TOL) break;
        md_prev = md;
        in = out;
        outIdx ^= 1;
        mdidx++;
    }

    // ---- final GEMM: out[j][q] = sum_n C[q,n] X[j,n] + sum_p D[q,p] U[j,p], k-split x8 ----
    {
        int kpart = bid >> 4;            // 0..7
        int jm = (bid & 15) * 128;       // m tile
#pragma unroll
        for (int mi = 0; mi < 4; mi++)
#pragma unroll
            for (int ni = 0; ni < 4; ni++)
#pragma unroll
                for (int r = 0; r < 4; r++) acc[mi][ni][r] = 0.f;
        int n_lo = kpart * (N_DIM / 8);
        gemm_tile<0>(Cm + n_lo, Cm + n_lo, N_DIM,
                     fin + (size_t)jm * N_DIM + n_lo, N_DIM, N_DIM / 8, 1, sm, acc);
        int p_lo = kpart * (P_DIM / 8);
        gemm_tile<0>(Dm + p_lo, Dm + p_lo, P_DIM,
                     U + (size_t)jm * P_DIM + p_lo, P_DIM, P_DIM / 8, 1, sm, acc);
        float* pp = g_part[kpart];
#pragma unroll
        for (int mi = 0; mi < 4; mi++)
#pragma unroll
            for (int ni = 0; ni < 4; ni++)
#pragma unroll
                for (int r = 0; r < 4; r++) {
                    int il = wm * 64 + mi * 16 + g + ((r >= 2) ? 8 : 0);   // q
                    int jl = wn * 32 + ni * 8 + 2 * c + (r & 1);           // m
                    pp[(size_t)(jm + jl) * Q_DIM + il] = acc[mi][ni][r];
                }
    }
    grid_bar(ep, tid);

    // ---- reduce partials -> output ----
    {
        size_t base = (size_t)bid * 512;   // float4 units; 128 x 512 = 65536 total
        float4* o = (float4*)outp;
        for (int i = tid; i < 512; i += 256) {
            float4 s4 = ((const float4*)g_part[0])[base + i];
#pragma unroll
            for (int p = 1; p < 8; p++) {
                float4 v = ((const float4*)g_part[p])[base + i];
                s4.x += v.x; s4.y += v.y; s4.z += v.z; s4.w += v.w;
            }
            o[base + i] = s4;
        }
    }
}

// ---------------- launcher ----------------
extern "C" void kernel_launch(void* const* d_in, const int* in_sizes, int n_in,
                              void* d_out, int out_size) {
    (void)in_sizes; (void)n_in; (void)out_size;
    const float* U  = (const float*)d_in[0];
    const float* X0 = (const float*)d_in[1];
    const float* A  = (const float*)d_in[2];
    const float* B  = (const float*)d_in[3];
    const float* Cm = (const float*)d_in[4];
    const float* Dm = (const float*)d_in[5];
    float* outp = (float*)d_out;

    cudaFuncSetAttribute(picard_kernel, cudaFuncAttributeMaxDynamicSharedMemorySize, DSMEM_BYTES);

    init_kernel<<<1, 256>>>();
    picard_kernel<<<NBLK, 256, DSMEM_BYTES>>>(A, X0, B, U, Cm, Dm, outp);
}